// round 7
// baseline (speedup 1.0000x reference)
#include <cuda_runtime.h>
#include <cuda_bf16.h>
#include <math.h>
#include <stdint.h>

#define BQ  128
#define KK_ 49
#define DD  512
#define EE  256
#define VV  10000
#define TT  20
#define G4  2048
#define NW  2176          // padded gates+Wg width: 2048 + 49 -> 17*128
typedef __nv_bfloat16 bf16;

// -------------------- device scratch (static) --------------------
__device__ __align__(128) bf16 g_embhi[BQ*TT*EE], g_emblo[BQ*TT*EE];
__device__ __align__(128) bf16 g_glhi[BQ*DD],     g_gllo[BQ*DD];
__device__ __align__(128) bf16 g_wihehi[G4*EE],   g_wihelo[G4*EE];
__device__ __align__(128) bf16 g_wcathi[3072*DD], g_wcatlo[3072*DD];  // [Winit_h;Winit_m;W_ih_D]
__device__ __align__(128) bf16 g_wc2hi[NW*DD],    g_wc2lo[NW*DD];     // [W_hh;Wg;0pad]
__device__ __align__(128) bf16 g_wvhi[KK_*DD],    g_wvlo[KK_*DD];
__device__ __align__(128) bf16 g_wphi[VV*DD],     g_wplo[VV*DD];
__device__ __align__(128) bf16 g_sphi[BQ*KK_*DD], g_splo[BQ*KK_*DD];
__device__ __align__(128) bf16 g_hhi[BQ*DD],      g_hlo[BQ*DD];
__device__ __align__(128) bf16 g_shi[BQ*TT*DD],   g_slo[BQ*TT*DD];
__device__ __align__(128) float g_gatesx[BQ*TT*G4];
__device__ __align__(128) float g_vproj[BQ*KK_*KK_];
__device__ __align__(128) float g_part[BQ*8*NW];
__device__ __align__(128) float g_ipart[4][BQ*3072];
__device__ __align__(128) float g_vpart[2][BQ*KK_*KK_];
__device__ unsigned g_barcnt = 0, g_bargen = 0;

// -------------------- helpers --------------------
__device__ __forceinline__ uint32_t su(const void* p) {
    return (uint32_t)__cvta_generic_to_shared(p);
}
__device__ __forceinline__ void cpa16(uint32_t sa, const void* ga, uint32_t sz) {
    asm volatile("cp.async.cg.shared.global [%0],[%1],16,%2;\n" :: "r"(sa), "l"(ga), "r"(sz));
}
__device__ __forceinline__ void cpcommit() { asm volatile("cp.async.commit_group;\n"); }
template<int N> __device__ __forceinline__ void cpwait() {
    asm volatile("cp.async.wait_group %0;\n" :: "n"(N));
}
__device__ __forceinline__ void ldsm4(uint32_t* r, uint32_t a) {
    asm volatile("ldmatrix.sync.aligned.m8n8.x4.shared.b16 {%0,%1,%2,%3},[%4];\n"
                 : "=r"(r[0]), "=r"(r[1]), "=r"(r[2]), "=r"(r[3]) : "r"(a));
}
__device__ __forceinline__ void mmab(float* c, const uint32_t* a, uint32_t b0, uint32_t b1) {
    asm volatile(
        "mma.sync.aligned.m16n8k16.row.col.f32.bf16.bf16.f32 "
        "{%0,%1,%2,%3},{%4,%5,%6,%7},{%8,%9},{%0,%1,%2,%3};\n"
        : "+f"(c[0]), "+f"(c[1]), "+f"(c[2]), "+f"(c[3])
        : "r"(a[0]), "r"(a[1]), "r"(a[2]), "r"(a[3]), "r"(b0), "r"(b1));
}
__device__ __forceinline__ void pack4(float4 v, uint2& uh, uint2& ul) {
    bf16 h0 = __float2bfloat16(v.x), h1 = __float2bfloat16(v.y);
    bf16 h2 = __float2bfloat16(v.z), h3 = __float2bfloat16(v.w);
    bf16 l0 = __float2bfloat16(v.x - __bfloat162float(h0));
    bf16 l1 = __float2bfloat16(v.y - __bfloat162float(h1));
    bf16 l2 = __float2bfloat16(v.z - __bfloat162float(h2));
    bf16 l3 = __float2bfloat16(v.w - __bfloat162float(h3));
    uh.x = ((uint32_t)__bfloat16_as_ushort(h1) << 16) | __bfloat16_as_ushort(h0);
    uh.y = ((uint32_t)__bfloat16_as_ushort(h3) << 16) | __bfloat16_as_ushort(h2);
    ul.x = ((uint32_t)__bfloat16_as_ushort(l1) << 16) | __bfloat16_as_ushort(l0);
    ul.y = ((uint32_t)__bfloat16_as_ushort(l3) << 16) | __bfloat16_as_ushort(l2);
}
__device__ __forceinline__ float fsig(float x) { return 1.f / (1.f + __expf(-x)); }
__device__ __forceinline__ float ftanh(float x) {
    float e = __expf(2.f * x);
    return 1.f - 2.f / (e + 1.f);
}

// one k16 step of a warp-tiled bf16x3 MMA (warp tile 64x32); STR = smem row stride
template<int STR>
__device__ __forceinline__ void mma_tile_k16(
    const bf16* A_h, const bf16* A_l, const bf16* B_h, const bf16* B_l,
    int ks, int wm, int wn, int lrow, int lcol, float acc[4][4][4])
{
    uint32_t ah[4][4], al[4][4], bh[2][4], bl[2][4];
#pragma unroll
    for (int mi = 0; mi < 4; mi++) {
        ldsm4(ah[mi], su(A_h + (wm * 64 + mi * 16 + lrow) * STR + ks + lcol));
        ldsm4(al[mi], su(A_l + (wm * 64 + mi * 16 + lrow) * STR + ks + lcol));
    }
#pragma unroll
    for (int p = 0; p < 2; p++) {
        ldsm4(bh[p], su(B_h + (wn * 32 + p * 16 + lrow) * STR + ks + lcol));
        ldsm4(bl[p], su(B_l + (wn * 32 + p * 16 + lrow) * STR + ks + lcol));
    }
#pragma unroll
    for (int mi = 0; mi < 4; mi++)
#pragma unroll
        for (int ni = 0; ni < 4; ni++) {
            const int p = ni >> 1, q = ni & 1;
            mmab(acc[mi][ni], ah[mi], bh[p][q], bh[p][q + 2]);
            mmab(acc[mi][ni], ah[mi], bl[p][q], bl[p][q + 2]);
            mmab(acc[mi][ni], al[mi], bh[p][q], bh[p][q + 2]);
        }
}

// -------------------- split/convert kernel --------------------
struct Seg { const float4* src; uint2* hi; uint2* lo; int srcld4; int lc4; long long start; };
struct SegArr { Seg s[10]; long long total; };

__global__ void split_all(SegArr sa) {
    long long i = (long long)blockIdx.x * blockDim.x + threadIdx.x;
    if (i >= sa.total) return;
    int k = 0;
#pragma unroll
    for (int j = 1; j < 10; j++) if (i >= sa.s[j].start) k = j;
    Seg sg = sa.s[k];
    long long idx = i - sg.start;
    int row = (int)(idx >> sg.lc4);
    int c   = (int)(idx & ((1 << sg.lc4) - 1));
    float4 v = sg.src[(long long)row * sg.srcld4 + c];
    uint2 uh, ul;
    pack4(v, uh, ul);
    sg.hi[idx] = uh;
    sg.lo[idx] = ul;
}

// -------------------- embedding gather (emits bf16 hi/lo) --------------------
__global__ void gather_emb(const int* __restrict__ cap, const float* __restrict__ emb) {
    int i = blockIdx.x * blockDim.x + threadIdx.x;
    if (i >= BQ * TT * (EE / 4)) return;
    int m = i >> 6, e4 = i & 63;
    int tok = cap[m];
    float4 v = reinterpret_cast<const float4*>(emb)[(size_t)tok * 64 + e4];
    uint2 uh, ul;
    pack4(v, uh, ul);
    reinterpret_cast<uint2*>(g_embhi)[(size_t)m * 64 + e4] = uh;
    reinterpret_cast<uint2*>(g_emblo)[(size_t)m * 64 + e4] = ul;
}

// -------------------- 2-stage pipelined bf16x3 GEMM (128x128, round-4 proven) --------
#define SST   40
#define SMATB (128 * SST)

__device__ __forceinline__ void gemm_issue(
    bf16* smbase,
    const bf16* __restrict__ Ah, const bf16* __restrict__ Al, int lda,
    const bf16* __restrict__ Bh, const bf16* __restrict__ Bl, int ldb,
    int bm, int bn, int N, int k0, int ldrow, int ldch)
{
    size_t aoff = (size_t)(bm + ldrow) * lda + k0 + ldch * 8;
    uint32_t sa = su(smbase + ldrow * SST + ldch * 8);
    cpa16(sa, Ah + aoff, 16);
    cpa16(sa + 16, Ah + aoff + 8, 16);
    uint32_t sa2 = sa + SMATB * 2;
    cpa16(sa2, Al + aoff, 16);
    cpa16(sa2 + 16, Al + aoff + 8, 16);

    int gn = bn + ldrow;
    uint32_t sz = (gn < N) ? 16u : 0u;
    int gnc = (gn < N) ? gn : 0;
    size_t boff = (size_t)gnc * ldb + k0 + ldch * 8;
    uint32_t sb = sa + 2 * SMATB * 2;
    cpa16(sb, Bh + boff, sz);
    cpa16(sb + 16, Bh + boff + 8, sz);
    uint32_t sb2 = sb + SMATB * 2;
    cpa16(sb2, Bl + boff, sz);
    cpa16(sb2 + 16, Bl + boff + 8, sz);
}

__global__ void __launch_bounds__(256, 2) gemm_hl(
    const bf16* __restrict__ Ah, const bf16* __restrict__ Al, int lda,
    const bf16* __restrict__ Bh, const bf16* __restrict__ Bl, int ldb,
    float* __restrict__ C, int ldc, int M, int N, int K,   // K = per-z slice length
    const float* __restrict__ bias,
    const int* __restrict__ mlen, int maskT,
    float* __restrict__ Cpart, long partStride)
{
    extern __shared__ __align__(16) char smraw[];
    bf16* sm = (bf16*)smraw;                     // [2][4][SMATB]

    const int tid = threadIdx.x;
    const int bm = blockIdx.y * 128, bn = blockIdx.x * 128;
    const int kz = blockIdx.z;
    const bf16* Ahz = Ah + (size_t)kz * K;
    const bf16* Alz = Al + (size_t)kz * K;
    const bf16* Bhz = Bh + (size_t)kz * K;
    const bf16* Blz = Bl + (size_t)kz * K;
    float* Cw = Cpart ? (Cpart + (size_t)kz * partStride) : C;

    const int w = tid >> 5, lane = tid & 31;
    const int wm = w >> 2, wn = w & 3;
    const int g = lane >> 2, tg = lane & 3;
    const int lrow = lane & 15, lcol = (lane >> 4) * 8;
    const int ldrow = tid >> 1, ldch = (tid & 1) * 2;

    float acc[4][4][4];
#pragma unroll
    for (int i = 0; i < 4; i++)
#pragma unroll
        for (int j = 0; j < 4; j++)
#pragma unroll
            for (int q = 0; q < 4; q++) acc[i][j][q] = 0.f;

    const int niter = K / 32;
    gemm_issue(sm, Ahz, Alz, lda, Bhz, Blz, ldb, bm, bn, N, 0, ldrow, ldch);
    cpcommit();
    int st = 0;
    for (int it = 0; it < niter; ++it) {
        if (it + 1 < niter) {
            gemm_issue(sm + (st ^ 1) * 4 * SMATB, Ahz, Alz, lda, Bhz, Blz, ldb,
                       bm, bn, N, (it + 1) * 32, ldrow, ldch);
            cpcommit();
            cpwait<1>();
        } else {
            cpwait<0>();
        }
        __syncthreads();
        const bf16* base = sm + st * 4 * SMATB;
#pragma unroll
        for (int ks = 0; ks < 32; ks += 16)
            mma_tile_k16<SST>(base, base + SMATB, base + 2 * SMATB, base + 3 * SMATB,
                              ks, wm, wn, lrow, lcol, acc);
        __syncthreads();
        st ^= 1;
    }

    // epilogue
#pragma unroll
    for (int mi = 0; mi < 4; mi++)
#pragma unroll
        for (int ni = 0; ni < 4; ni++) {
            int gn0 = bn + wn * 32 + ni * 8 + tg * 2;
#pragma unroll
            for (int half = 0; half < 2; half++) {
                int gm = bm + wm * 64 + mi * 16 + g + half * 8;
                if (gm >= M) continue;
                bool zero = mlen ? (mlen[gm / maskT] <= (gm % maskT)) : false;
#pragma unroll
                for (int q = 0; q < 2; q++) {
                    int gn = gn0 + q;
                    if (gn >= N) continue;
                    float v = acc[mi][ni][half * 2 + q];
                    if (bias) v += bias[gn];
                    if (zero) v = 0.f;
                    Cw[(size_t)gm * ldc + gn] = v;
                }
            }
        }
}

// -------------------- 3-stage 256x128 bf16x3 GEMM (512 threads, 1 sync/iter) --------
#define BST   40
#define B_A   (256 * BST)              // elems per A matrix per stage
#define B_B   (128 * BST)
#define BSTGE (2 * B_A + 2 * B_B)      // elems per stage

__global__ void __launch_bounds__(512, 1) gemm_big(
    const bf16* __restrict__ Ah, const bf16* __restrict__ Al, int lda,
    const bf16* __restrict__ Bh, const bf16* __restrict__ Bl, int ldb,
    float* __restrict__ C, int ldc, int M, int N, int K,
    const float* __restrict__ bias,
    const int* __restrict__ mlen, int maskT)
{
    extern __shared__ __align__(16) char smraw[];
    bf16* sm = (bf16*)smraw;                     // [3][BSTGE]

    const int tid = threadIdx.x;
    const int bm = blockIdx.y * 256, bn = blockIdx.x * 128;

    const int w = tid >> 5, lane = tid & 31;
    const int wm = w >> 2, wn = w & 3;           // 4x4 warp grid: 64x32 warp tile
    const int g = lane >> 2, tg = lane & 3;
    const int lrow = lane & 15, lcol = (lane >> 4) * 8;

    // loader roles: all 512 threads load A (2/row); tid>=256 also load B (2/row)
    const int arow = tid >> 1, ach = (tid & 1) * 16;
    const bf16* aHi = Ah + (size_t)(bm + arow) * lda + ach;
    const bf16* aLo = Al + (size_t)(bm + arow) * lda + ach;
    const int brow = (tid - 256) >> 1, bch = (tid & 1) * 16;
    int gn_l = bn + brow;
    uint32_t szb = (tid >= 256 && gn_l < N) ? 16u : 0u;
    if (gn_l >= N) gn_l = 0;
    const bf16* bHi = Bh + (size_t)gn_l * ldb + bch;
    const bf16* bLo = Bl + (size_t)gn_l * ldb + bch;
    const uint32_t da = su(sm + arow * BST + ach);
    const uint32_t db = su(sm + 2 * B_A + brow * BST + bch);

    float acc[4][4][4];
#pragma unroll
    for (int i = 0; i < 4; i++)
#pragma unroll
        for (int j = 0; j < 4; j++)
#pragma unroll
            for (int q = 0; q < 4; q++) acc[i][j][q] = 0.f;

    auto issue = [&](int stg, int k0) {
        uint32_t so = (uint32_t)(stg * BSTGE) * 2;
        cpa16(da + so,              aHi + k0,     16);
        cpa16(da + so + 16,         aHi + k0 + 8, 16);
        cpa16(da + so + B_A * 2,      aLo + k0,     16);
        cpa16(da + so + B_A * 2 + 16, aLo + k0 + 8, 16);
        if (tid >= 256) {
            cpa16(db + so,              bHi + k0,     szb);
            cpa16(db + so + 16,         bHi + k0 + 8, szb);
            cpa16(db + so + B_B * 2,      bLo + k0,     szb);
            cpa16(db + so + B_B * 2 + 16, bLo + k0 + 8, szb);
        }
    };

    const int niter = K / 32;
    issue(0, 0);  cpcommit();
    issue(1, 32); cpcommit();

    for (int it = 0; it < niter; ++it) {
        cpwait<1>();
        __syncthreads();          // data visible to all warps; prior compute on the
        {                         // stage about to be overwritten is done (sync order)
            int nx = it + 2;
            if (nx < niter) issue(nx % 3, nx * 32);
            cpcommit();
        }
        const bf16* base = sm + (it % 3) * BSTGE;
#pragma unroll
        for (int ks = 0; ks < 32; ks += 16)
            mma_tile_k16<BST>(base, base + B_A, base + 2 * B_A, base + 2 * B_A + B_B,
                              ks, wm, wn, lrow, lcol, acc);
    }

    // epilogue
#pragma unroll
    for (int mi = 0; mi < 4; mi++)
#pragma unroll
        for (int ni = 0; ni < 4; ni++) {
            int gn0 = bn + wn * 32 + ni * 8 + tg * 2;
#pragma unroll
            for (int half = 0; half < 2; half++) {
                int gm = bm + wm * 64 + mi * 16 + g + half * 8;
                if (gm >= M) continue;
                bool zero = mlen ? (mlen[gm / maskT] <= (gm % maskT)) : false;
#pragma unroll
                for (int q = 0; q < 2; q++) {
                    int gn = gn0 + q;
                    if (gn >= N) continue;
                    float v = acc[mi][ni][half * 2 + q];
                    if (bias) v += bias[gn];
                    if (zero) v = 0.f;
                    C[(size_t)gm * ldc + gn] = v;
                }
            }
        }
}

// -------------------- cheap grid barrier (acq/rel) --------------------
__device__ __forceinline__ void gridbar() {
    __syncthreads();
    if (threadIdx.x == 0) {
        unsigned gen = *(volatile unsigned*)&g_bargen;
        unsigned old;
        asm volatile("atom.add.release.gpu.u32 %0,[%1],1;"
                     : "=r"(old) : "l"(&g_barcnt) : "memory");
        if (old == gridDim.x - 1) {
            g_barcnt = 0;
            asm volatile("st.release.gpu.u32 [%0],%1;"
                         :: "l"(&g_bargen), "r"(gen + 1) : "memory");
        } else {
            unsigned v;
            do {
                asm volatile("ld.acquire.gpu.u32 %0,[%1];"
                             : "=r"(v) : "l"(&g_bargen) : "memory");
            } while (v == gen);
        }
    }
    __syncthreads();
}

// -------------------- persistent recurrence kernel --------------------
#define RST 72
#define RMATB (128 * RST)

__global__ __launch_bounds__(256, 1) void recur_kernel(
    const float* __restrict__ b_hh,
    const int*   __restrict__ lengths,
    const float* __restrict__ spatial,
    const float* __restrict__ bg,
    const float* __restrict__ wh,
    const float* __restrict__ bh_att,
    const float* __restrict__ b_init_h,
    const float* __restrict__ b_init_m,
    const float* __restrict__ b_ih,
    const float* __restrict__ bv)
{
    extern __shared__ __align__(16) char dsm[];
    bf16* sAh = (bf16*)dsm;
    bf16* sAl = sAh + RMATB;
    bf16* sBh = sAl + RMATB;
    bf16* sBl = sBh + RMATB;
    float* sh_gh    = (float*)(dsm + 4 * RMATB * 2);
    float* sh_z     = sh_gh + 52;
    float* sh_alpha = sh_z + 52;

    const int c = blockIdx.x;
    const int tid = threadIdx.x;
    const int kc = c & 7, cg = c >> 3, kbase = kc * 64;   // cg in 0..16
    const int b = c;                                      // phase2 owner (b<128 only)
    const int w = tid >> 5, lane = tid & 31;
    const int wm = w >> 2, wn = w & 3;
    const int g = lane >> 2, tg = lane & 3;
    const int lrow = lane & 15, lcol = (lane >> 4) * 8;
    const int wid = w;
    const float bh0 = bh_att[0];

    float hp[2], mr[2], gb[8];   // register-resident recurrent state
    int len = 0;

    // ---- prologue: per-batch init reduce + W_cat slice preload ----
    if (b < BQ) {
        len = lengths[b];
#pragma unroll
        for (int j = 0; j < 12; j++) {
            int n = tid + j * 256;
            float v = g_ipart[0][b * 3072 + n] + g_ipart[1][b * 3072 + n]
                    + g_ipart[2][b * 3072 + n] + g_ipart[3][b * 3072 + n];
            if (j < 2) {
                v += b_init_h[n];
                hp[j] = v;
                bf16 hh = __float2bfloat16(v);
                g_hhi[b * DD + n] = hh;
                g_hlo[b * DD + n] = __float2bfloat16(v - __bfloat162float(hh));
            } else if (j < 4) {
                mr[j - 2] = v + b_init_m[n - 512];
            } else {
                int col = n - 1024;
                gb[j - 4] = v + b_ih[col] + b_hh[col];
            }
        }
        for (int i = tid; i < KK_ * KK_; i += 256) {
            int r = b * KK_ + i / KK_, q = i % KK_;
            g_vproj[(size_t)r * KK_ + q] =
                g_vpart[0][(size_t)r * KK_ + q] + g_vpart[1][(size_t)r * KK_ + q] + bv[q];
        }
    }
#pragma unroll
    for (int j = 0; j < 4; j++) {
        int cid = tid + j * 256;
        int row = cid >> 3, ch = cid & 7;
        *(float4*)(sBh + row * RST + ch * 8) =
            *(const float4*)(g_wc2hi + (size_t)(cg * 128 + row) * DD + kbase + ch * 8);
        *(float4*)(sBl + row * RST + ch * 8) =
            *(const float4*)(g_wc2lo + (size_t)(cg * 128 + row) * DD + kbase + ch * 8);
    }
    gridbar();   // h0 + vproj visible to all CTAs

    for (int t = 0; t <= TT; t++) {
        // ---------------- GEMM: [gates(t); gh(t-1)] = h(t-1) @ W_cat^T ----------------
        {
#pragma unroll
            for (int j = 0; j < 4; j++) {
                int cid = tid + j * 256;
                int row = cid >> 3, ch = cid & 7;
                *(float4*)(sAh + row * RST + ch * 8) =
                    *(const float4*)(g_hhi + (size_t)row * DD + kbase + ch * 8);
                *(float4*)(sAl + row * RST + ch * 8) =
                    *(const float4*)(g_hlo + (size_t)row * DD + kbase + ch * 8);
            }
            __syncthreads();

            float acc[4][4][4];
#pragma unroll
            for (int i = 0; i < 4; i++)
#pragma unroll
                for (int j = 0; j < 4; j++)
#pragma unroll
                    for (int q = 0; q < 4; q++) acc[i][j][q] = 0.f;

#pragma unroll
            for (int ks = 0; ks < 64; ks += 16)
                mma_tile_k16<RST>(sAh, sAl, sBh, sBl, ks, wm, wn, lrow, lcol, acc);

#pragma unroll
            for (int mi = 0; mi < 4; mi++)
#pragma unroll
                for (int ni = 0; ni < 4; ni++) {
                    int gn0 = wn * 32 + ni * 8 + tg * 2;
#pragma unroll
                    for (int half = 0; half < 2; half++) {
                        int gm = wm * 64 + mi * 16 + g + half * 8;   // batch row
                        float* pr = g_part + (size_t)gm * (8 * NW) + kc * NW + cg * 128 + gn0;
                        pr[0] = acc[mi][ni][half * 2 + 0];
                        pr[1] = acc[mi][ni][half * 2 + 1];
                    }
                }
        }
        gridbar();
        // ---------------- phase 2 (CTA b < 128) ----------------
        if (b < BQ) {
            const float* pp = g_part + (size_t)b * (8 * NW);
            // ---- attention for step t-1 ----
            if (t >= 1 && len > t - 1) {
                if (tid < KK_) {
                    float s = bg[tid];
#pragma unroll
                    for (int q = 0; q < 8; q++) s += pp[q * NW + 2048 + tid];
                    sh_gh[tid] = s;
                }
                __syncthreads();
                for (int k = wid; k < KK_; k += 8) {
                    const float* vp = g_vproj + (size_t)(b * KK_ + k) * KK_;
                    float s = 0.f;
                    for (int q = lane; q < KK_; q += 32) s += ftanh(vp[q] + sh_gh[q]) * wh[q];
#pragma unroll
                    for (int o = 16; o; o >>= 1) s += __shfl_xor_sync(0xffffffffu, s, o);
                    if (lane == 0) sh_z[k] = s + bh0;
                }
                __syncthreads();
                if (wid == 0) {
                    float mx = -3.0e38f;
                    for (int k = lane; k < KK_; k += 32) mx = fmaxf(mx, sh_z[k]);
#pragma unroll
                    for (int o = 16; o; o >>= 1) mx = fmaxf(mx, __shfl_xor_sync(0xffffffffu, mx, o));
                    float sm = 0.f;
                    for (int k = lane; k < KK_; k += 32) { float e = __expf(sh_z[k] - mx); sh_alpha[k] = e; sm += e; }
#pragma unroll
                    for (int o = 16; o; o >>= 1) sm += __shfl_xor_sync(0xffffffffu, sm, o);
                    float inv = 1.f / sm;
                    for (int k = lane; k < KK_; k += 32) sh_alpha[k] *= inv;
                }
                __syncthreads();
                const float* sp = spatial + (size_t)b * KK_ * DD;
#pragma unroll
                for (int j = 0; j < 2; j++) {
                    int d = tid + j * 256;
                    float cc = 0.f;
#pragma unroll
                    for (int k = 0; k < KK_; k++) cc = fmaf(sh_alpha[k], sp[(size_t)k * DD + d], cc);
                    float sv = cc + hp[j];
                    bf16 shh = __float2bfloat16(sv);
                    g_shi[(size_t)(b * TT + t - 1) * DD + d] = shh;
                    g_slo[(size_t)(b * TT + t - 1) * DD + d] = __float2bfloat16(sv - __bfloat162float(shh));
                }
            }
            // ---- LSTM for step t ----
            if (t < TT && len > t) {
                const float* gx = g_gatesx + (size_t)(b * TT + t) * G4;
#pragma unroll
                for (int j = 0; j < 2; j++) {
                    int d = tid + j * 256;
                    float gi = gx[d]        + gb[j];
                    float gf = gx[512 + d]  + gb[2 + j];
                    float gg = gx[1024 + d] + gb[4 + j];
                    float go = gx[1536 + d] + gb[6 + j];
#pragma unroll
                    for (int q = 0; q < 8; q++) {
                        const float* p = pp + q * NW;
                        gi += p[d]; gf += p[512 + d]; gg += p[1024 + d]; go += p[1536 + d];
                    }
                    float ig = fsig(gi), fg = fsig(gf), og = fsig(go);
                    float gt = ftanh(gg);
                    float mn = fg * mr[j] + ig * gt;
                    float hv = og * ftanh(mn);
                    mr[j] = mn;
                    hp[j] = hv;
                    bf16 hh = __float2bfloat16(hv);
                    g_hhi[(size_t)b * DD + d] = hh;
                    g_hlo[(size_t)b * DD + d] = __float2bfloat16(hv - __bfloat162float(hh));
                }
            }
        }
        gridbar();
    }
}

// -------------------- launch --------------------
extern "C" void kernel_launch(void* const* d_in, const int* in_sizes, int n_in,
                              void* d_out, int out_size)
{
    const float* spatial      = (const float*)d_in[0];
    const float* global_feats = (const float*)d_in[1];
    const int*   captions     = (const int*)d_in[2];
    const int*   lengths      = (const int*)d_in[3];
    const float* emb          = (const float*)d_in[4];
    const float* W_init_h     = (const float*)d_in[5];
    const float* b_init_h     = (const float*)d_in[6];
    const float* W_init_m     = (const float*)d_in[7];
    const float* b_init_m     = (const float*)d_in[8];
    const float* W_ih         = (const float*)d_in[9];
    const float* b_ih         = (const float*)d_in[10];
    const float* W_hh         = (const float*)d_in[11];
    const float* b_hh         = (const float*)d_in[12];
    const float* Wv           = (const float*)d_in[13];
    const float* bv           = (const float*)d_in[14];
    const float* Wg           = (const float*)d_in[15];
    const float* bg           = (const float*)d_in[16];
    const float* wh           = (const float*)d_in[17];
    const float* bh_att       = (const float*)d_in[18];
    const float* Wp           = (const float*)d_in[19];
    const float* bp           = (const float*)d_in[20];
    float* out = (float*)d_out;

#define GETP(var, sym) void* var; cudaGetSymbolAddress(&var, sym)
    GETP(p_embhi, g_embhi);  GETP(p_emblo, g_emblo);
    GETP(p_glhi, g_glhi);    GETP(p_gllo, g_gllo);
    GETP(p_wihehi, g_wihehi);GETP(p_wihelo, g_wihelo);
    GETP(p_wcathi, g_wcathi);GETP(p_wcatlo, g_wcatlo);
    GETP(p_wc2hi, g_wc2hi);  GETP(p_wc2lo, g_wc2lo);
    GETP(p_wvhi, g_wvhi);    GETP(p_wvlo, g_wvlo);
    GETP(p_wphi, g_wphi);    GETP(p_wplo, g_wplo);
    GETP(p_sphi, g_sphi);    GETP(p_splo, g_splo);
    GETP(p_shi, g_shi);      GETP(p_slo, g_slo);
    GETP(p_gatesx, g_gatesx);
    GETP(p_ipart, g_ipart);  GETP(p_vpart, g_vpart);
#undef GETP

    const int GSM  = 2 * 4 * SMATB * 2;                      // 81920 B
    const int BGSM = 3 * BSTGE * 2;                          // 184320 B
    const int RSM  = 4 * RMATB * 2 + (3 * 52) * 4;
    cudaFuncSetAttribute(gemm_hl, cudaFuncAttributeMaxDynamicSharedMemorySize, GSM);
    cudaFuncSetAttribute(gemm_big, cudaFuncAttributeMaxDynamicSharedMemorySize, BGSM);
    cudaFuncSetAttribute(recur_kernel, cudaFuncAttributeMaxDynamicSharedMemorySize, RSM);

    // ---- 1. split all fp32 operands into bf16 hi/lo ----
    SegArr sa;
    long long pos = 0;
    auto seg = [&](int i, const float* src, void* hi, void* lo, int srcld, int cols, int rows) {
        sa.s[i].src = (const float4*)src;
        sa.s[i].hi = (uint2*)hi;  sa.s[i].lo = (uint2*)lo;
        sa.s[i].srcld4 = srcld / 4;
        sa.s[i].lc4 = (cols / 4 == 64) ? 6 : 7;
        sa.s[i].start = pos;
        pos += (long long)rows * (cols / 4);
    };
    seg(0, global_feats, p_glhi, p_gllo, DD, DD, BQ);
    seg(1, W_init_h, p_wcathi, p_wcatlo, DD, DD, DD);
    seg(2, W_init_m, (bf16*)p_wcathi + 512 * DD, (bf16*)p_wcatlo + 512 * DD, DD, DD, DD);
    seg(3, W_ih, p_wihehi, p_wihelo, EE + DD, EE, G4);
    seg(4, W_ih + EE, (bf16*)p_wcathi + 1024 * DD, (bf16*)p_wcatlo + 1024 * DD, EE + DD, DD, G4);
    seg(5, W_hh, p_wc2hi, p_wc2lo, DD, DD, G4);
    seg(6, Wg, (bf16*)p_wc2hi + 2048 * DD, (bf16*)p_wc2lo + 2048 * DD, DD, DD, KK_);
    seg(7, Wv, p_wvhi, p_wvlo, DD, DD, KK_);
    seg(8, Wp, p_wphi, p_wplo, DD, DD, VV);
    seg(9, spatial, p_sphi, p_splo, DD, DD, BQ * KK_);
    sa.total = pos;
    split_all<<<(unsigned)((pos + 255) / 256), 256>>>(sa);

    // ---- 2. gather caption embeddings (bf16 hi/lo) ----
    gather_emb<<<(BQ * TT * (EE / 4) + 255) / 256, 256>>>(captions, emb);

    // ---- 3. vproj partials: spatial @ Wv^T, split-K x2 ----
    gemm_hl<<<dim3(1, 49, 2), 256, GSM>>>((bf16*)p_sphi, (bf16*)p_splo, DD,
        (bf16*)p_wvhi, (bf16*)p_wvlo, DD, nullptr, KK_, BQ * KK_, KK_, 256,
        nullptr, nullptr, 1, (float*)p_vpart, (long)BQ * KK_ * KK_);

    // ---- 4. gates_x = embseq @ W_ih[:,:E]^T (256x128-tile pipeline) ----
    gemm_big<<<dim3(16, 10), 512, BGSM>>>((bf16*)p_embhi, (bf16*)p_emblo, EE,
        (bf16*)p_wihehi, (bf16*)p_wihelo, EE, (float*)p_gatesx, G4, BQ * TT, G4, EE,
        nullptr, nullptr, 1);

    // ---- 5. init partials: global @ [Winit_h;Winit_m;W_ihD]^T, split-K x4 ----
    gemm_hl<<<dim3(24, 1, 4), 256, GSM>>>((bf16*)p_glhi, (bf16*)p_gllo, DD,
        (bf16*)p_wcathi, (bf16*)p_wcatlo, DD, nullptr, 3072, BQ, 3072, 128,
        nullptr, nullptr, 1, (float*)p_ipart, (long)BQ * 3072);

    // ---- 6. recurrence ----
    recur_kernel<<<136, 256, RSM>>>(b_hh, lengths, spatial, bg, wh, bh_att,
                                    b_init_h, b_init_m, b_ih, bv);

    // ---- 7. logits = s @ Wp^T + bp (masked, 256x128-tile pipeline) ----
    gemm_big<<<dim3(79, 10), 512, BGSM>>>((bf16*)p_shi, (bf16*)p_slo, DD,
        (bf16*)p_wphi, (bf16*)p_wplo, DD, out, VV, BQ * TT, VV, DD,
        bp, lengths, TT);
}

// round 9
// speedup vs baseline: 1.3694x; 1.3694x over previous
#include <cuda_runtime.h>
#include <cuda_bf16.h>
#include <cuda_fp16.h>
#include <math.h>
#include <stdint.h>

#define BQ  128
#define KK_ 49
#define DD  512
#define EE  256
#define VV  10000
#define TT  20
#define G4  2048
#define NW  2176          // padded gates+Wg width: 2048 + 49 -> 17*128
typedef __nv_bfloat16 bf16;
typedef __half fp16;

// -------------------- device scratch (static) --------------------
__device__ __align__(128) bf16 g_embhi[BQ*TT*EE], g_emblo[BQ*TT*EE];
__device__ __align__(128) bf16 g_glhi[BQ*DD],     g_gllo[BQ*DD];
__device__ __align__(128) bf16 g_wihehi[G4*EE],   g_wihelo[G4*EE];
__device__ __align__(128) bf16 g_wcathi[3072*DD], g_wcatlo[3072*DD];  // [Winit_h;Winit_m;W_ih_D]
__device__ __align__(128) bf16 g_wc2hi[NW*DD],    g_wc2lo[NW*DD];     // [W_hh;Wg;0pad]
__device__ __align__(128) bf16 g_wvhi[KK_*DD],    g_wvlo[KK_*DD];
__device__ __align__(128) bf16 g_sphi[BQ*KK_*DD], g_splo[BQ*KK_*DD];
__device__ __align__(128) bf16 g_hhi[BQ*DD],      g_hlo[BQ*DD];
__device__ __align__(128) fp16 g_wpf[VV*DD];      // Wp in fp16
__device__ __align__(128) fp16 g_sf[BQ*TT*DD];    // s_t in fp16
__device__ __align__(128) float g_gatesx[BQ*TT*G4];
__device__ __align__(128) float g_vproj[BQ*KK_*KK_];
__device__ __align__(128) float g_part[BQ*8*NW];
__device__ __align__(128) float g_ipart[4][BQ*3072];
__device__ __align__(128) float g_vpart[2][BQ*KK_*KK_];
__device__ unsigned g_barcnt = 0, g_bargen = 0;

// -------------------- helpers --------------------
__device__ __forceinline__ uint32_t su(const void* p) {
    return (uint32_t)__cvta_generic_to_shared(p);
}
__device__ __forceinline__ void cpa16(uint32_t sa, const void* ga, uint32_t sz) {
    asm volatile("cp.async.cg.shared.global [%0],[%1],16,%2;\n" :: "r"(sa), "l"(ga), "r"(sz));
}
__device__ __forceinline__ void cpcommit() { asm volatile("cp.async.commit_group;\n"); }
template<int N> __device__ __forceinline__ void cpwait() {
    asm volatile("cp.async.wait_group %0;\n" :: "n"(N));
}
__device__ __forceinline__ void ldsm4(uint32_t* r, uint32_t a) {
    asm volatile("ldmatrix.sync.aligned.m8n8.x4.shared.b16 {%0,%1,%2,%3},[%4];\n"
                 : "=r"(r[0]), "=r"(r[1]), "=r"(r[2]), "=r"(r[3]) : "r"(a));
}
__device__ __forceinline__ void mmab(float* c, const uint32_t* a, uint32_t b0, uint32_t b1) {
    asm volatile(
        "mma.sync.aligned.m16n8k16.row.col.f32.bf16.bf16.f32 "
        "{%0,%1,%2,%3},{%4,%5,%6,%7},{%8,%9},{%0,%1,%2,%3};\n"
        : "+f"(c[0]), "+f"(c[1]), "+f"(c[2]), "+f"(c[3])
        : "r"(a[0]), "r"(a[1]), "r"(a[2]), "r"(a[3]), "r"(b0), "r"(b1));
}
__device__ __forceinline__ void mmah(float* c, const uint32_t* a, uint32_t b0, uint32_t b1) {
    asm volatile(
        "mma.sync.aligned.m16n8k16.row.col.f32.f16.f16.f32 "
        "{%0,%1,%2,%3},{%4,%5,%6,%7},{%8,%9},{%0,%1,%2,%3};\n"
        : "+f"(c[0]), "+f"(c[1]), "+f"(c[2]), "+f"(c[3])
        : "r"(a[0]), "r"(a[1]), "r"(a[2]), "r"(a[3]), "r"(b0), "r"(b1));
}
__device__ __forceinline__ void pack4(float4 v, uint2& uh, uint2& ul) {
    bf16 h0 = __float2bfloat16(v.x), h1 = __float2bfloat16(v.y);
    bf16 h2 = __float2bfloat16(v.z), h3 = __float2bfloat16(v.w);
    bf16 l0 = __float2bfloat16(v.x - __bfloat162float(h0));
    bf16 l1 = __float2bfloat16(v.y - __bfloat162float(h1));
    bf16 l2 = __float2bfloat16(v.z - __bfloat162float(h2));
    bf16 l3 = __float2bfloat16(v.w - __bfloat162float(h3));
    uh.x = ((uint32_t)__bfloat16_as_ushort(h1) << 16) | __bfloat16_as_ushort(h0);
    uh.y = ((uint32_t)__bfloat16_as_ushort(h3) << 16) | __bfloat16_as_ushort(h2);
    ul.x = ((uint32_t)__bfloat16_as_ushort(l1) << 16) | __bfloat16_as_ushort(l0);
    ul.y = ((uint32_t)__bfloat16_as_ushort(l3) << 16) | __bfloat16_as_ushort(l2);
}
__device__ __forceinline__ float fsig(float x) { return 1.f / (1.f + __expf(-x)); }
__device__ __forceinline__ float ftanh(float x) {
    float e = __expf(2.f * x);
    return 1.f - 2.f / (e + 1.f);
}

// one k16 step of warp-tiled bf16x3 MMA (warp tile 64x32); STR = smem row stride
template<int STR>
__device__ __forceinline__ void mma_tile_k16(
    const bf16* A_h, const bf16* A_l, const bf16* B_h, const bf16* B_l,
    int ks, int wm, int wn, int lrow, int lcol, float acc[4][4][4])
{
    uint32_t ah[4][4], al[4][4], bh[2][4], bl[2][4];
#pragma unroll
    for (int mi = 0; mi < 4; mi++) {
        ldsm4(ah[mi], su(A_h + (wm * 64 + mi * 16 + lrow) * STR + ks + lcol));
        ldsm4(al[mi], su(A_l + (wm * 64 + mi * 16 + lrow) * STR + ks + lcol));
    }
#pragma unroll
    for (int p = 0; p < 2; p++) {
        ldsm4(bh[p], su(B_h + (wn * 32 + p * 16 + lrow) * STR + ks + lcol));
        ldsm4(bl[p], su(B_l + (wn * 32 + p * 16 + lrow) * STR + ks + lcol));
    }
#pragma unroll
    for (int mi = 0; mi < 4; mi++)
#pragma unroll
        for (int ni = 0; ni < 4; ni++) {
            const int p = ni >> 1, q = ni & 1;
            mmab(acc[mi][ni], ah[mi], bh[p][q], bh[p][q + 2]);
            mmab(acc[mi][ni], ah[mi], bl[p][q], bl[p][q + 2]);
            mmab(acc[mi][ni], al[mi], bh[p][q], bh[p][q + 2]);
        }
}

// -------------------- split/convert kernel --------------------
struct Seg { const float4* src; uint2* hi; uint2* lo; int srcld4; int lc4; long long start; };
struct SegArr { Seg s[9]; long long total; };

__global__ void split_all(SegArr sa) {
    long long i = (long long)blockIdx.x * blockDim.x + threadIdx.x;
    if (i >= sa.total) return;
    int k = 0;
#pragma unroll
    for (int j = 1; j < 9; j++) if (i >= sa.s[j].start) k = j;
    Seg sg = sa.s[k];
    long long idx = i - sg.start;
    int row = (int)(idx >> sg.lc4);
    int c   = (int)(idx & ((1 << sg.lc4) - 1));
    float4 v = sg.src[(long long)row * sg.srcld4 + c];
    uint2 uh, ul;
    pack4(v, uh, ul);
    sg.hi[idx] = uh;
    sg.lo[idx] = ul;
}

// -------------------- fp32 -> fp16 convert (for Wp) --------------------
__global__ void conv_half(const float4* __restrict__ src, uint2* __restrict__ dst, int n4) {
    int i = blockIdx.x * blockDim.x + threadIdx.x;
    if (i >= n4) return;
    float4 v = src[i];
    __half2 a = __floats2half2_rn(v.x, v.y);
    __half2 b = __floats2half2_rn(v.z, v.w);
    uint2 o;
    o.x = *reinterpret_cast<uint32_t*>(&a);
    o.y = *reinterpret_cast<uint32_t*>(&b);
    dst[i] = o;
}

// -------------------- embedding gather (emits bf16 hi/lo) --------------------
__global__ void gather_emb(const int* __restrict__ cap, const float* __restrict__ emb) {
    int i = blockIdx.x * blockDim.x + threadIdx.x;
    if (i >= BQ * TT * (EE / 4)) return;
    int m = i >> 6, e4 = i & 63;
    int tok = cap[m];
    float4 v = reinterpret_cast<const float4*>(emb)[(size_t)tok * 64 + e4];
    uint2 uh, ul;
    pack4(v, uh, ul);
    reinterpret_cast<uint2*>(g_embhi)[(size_t)m * 64 + e4] = uh;
    reinterpret_cast<uint2*>(g_emblo)[(size_t)m * 64 + e4] = ul;
}

// -------------------- 2-stage pipelined bf16x3 GEMM (128x128) --------------------
#define SST   40
#define SMATB (128 * SST)

__device__ __forceinline__ void gemm_issue(
    bf16* smbase,
    const bf16* __restrict__ Ah, const bf16* __restrict__ Al, int lda,
    const bf16* __restrict__ Bh, const bf16* __restrict__ Bl, int ldb,
    int bm, int bn, int N, int k0, int ldrow, int ldch)
{
    size_t aoff = (size_t)(bm + ldrow) * lda + k0 + ldch * 8;
    uint32_t sa = su(smbase + ldrow * SST + ldch * 8);
    cpa16(sa, Ah + aoff, 16);
    cpa16(sa + 16, Ah + aoff + 8, 16);
    uint32_t sa2 = sa + SMATB * 2;
    cpa16(sa2, Al + aoff, 16);
    cpa16(sa2 + 16, Al + aoff + 8, 16);

    int gn = bn + ldrow;
    uint32_t sz = (gn < N) ? 16u : 0u;
    int gnc = (gn < N) ? gn : 0;
    size_t boff = (size_t)gnc * ldb + k0 + ldch * 8;
    uint32_t sb = sa + 2 * SMATB * 2;
    cpa16(sb, Bh + boff, sz);
    cpa16(sb + 16, Bh + boff + 8, sz);
    uint32_t sb2 = sb + SMATB * 2;
    cpa16(sb2, Bl + boff, sz);
    cpa16(sb2 + 16, Bl + boff + 8, sz);
}

__global__ void __launch_bounds__(256, 2) gemm_hl(
    const bf16* __restrict__ Ah, const bf16* __restrict__ Al, int lda,
    const bf16* __restrict__ Bh, const bf16* __restrict__ Bl, int ldb,
    float* __restrict__ C, int ldc, int M, int N, int K,
    const float* __restrict__ bias,
    const int* __restrict__ mlen, int maskT,
    float* __restrict__ Cpart, long partStride)
{
    extern __shared__ __align__(16) char smraw[];
    bf16* sm = (bf16*)smraw;

    const int tid = threadIdx.x;
    const int bm = blockIdx.y * 128, bn = blockIdx.x * 128;
    const int kz = blockIdx.z;
    const bf16* Ahz = Ah + (size_t)kz * K;
    const bf16* Alz = Al + (size_t)kz * K;
    const bf16* Bhz = Bh + (size_t)kz * K;
    const bf16* Blz = Bl + (size_t)kz * K;
    float* Cw = Cpart ? (Cpart + (size_t)kz * partStride) : C;

    const int w = tid >> 5, lane = tid & 31;
    const int wm = w >> 2, wn = w & 3;
    const int g = lane >> 2, tg = lane & 3;
    const int lrow = lane & 15, lcol = (lane >> 4) * 8;
    const int ldrow = tid >> 1, ldch = (tid & 1) * 2;

    float acc[4][4][4];
#pragma unroll
    for (int i = 0; i < 4; i++)
#pragma unroll
        for (int j = 0; j < 4; j++)
#pragma unroll
            for (int q = 0; q < 4; q++) acc[i][j][q] = 0.f;

    const int niter = K / 32;
    gemm_issue(sm, Ahz, Alz, lda, Bhz, Blz, ldb, bm, bn, N, 0, ldrow, ldch);
    cpcommit();
    int st = 0;
    for (int it = 0; it < niter; ++it) {
        if (it + 1 < niter) {
            gemm_issue(sm + (st ^ 1) * 4 * SMATB, Ahz, Alz, lda, Bhz, Blz, ldb,
                       bm, bn, N, (it + 1) * 32, ldrow, ldch);
            cpcommit();
            cpwait<1>();
        } else {
            cpwait<0>();
        }
        __syncthreads();
        const bf16* base = sm + st * 4 * SMATB;
#pragma unroll
        for (int ks = 0; ks < 32; ks += 16)
            mma_tile_k16<SST>(base, base + SMATB, base + 2 * SMATB, base + 3 * SMATB,
                              ks, wm, wn, lrow, lcol, acc);
        __syncthreads();
        st ^= 1;
    }

#pragma unroll
    for (int mi = 0; mi < 4; mi++)
#pragma unroll
        for (int ni = 0; ni < 4; ni++) {
            int gn0 = bn + wn * 32 + ni * 8 + tg * 2;
#pragma unroll
            for (int half = 0; half < 2; half++) {
                int gm = bm + wm * 64 + mi * 16 + g + half * 8;
                if (gm >= M) continue;
                bool zero = mlen ? (mlen[gm / maskT] <= (gm % maskT)) : false;
#pragma unroll
                for (int q = 0; q < 2; q++) {
                    int gn = gn0 + q;
                    if (gn >= N) continue;
                    float v = acc[mi][ni][half * 2 + q];
                    if (bias) v += bias[gn];
                    if (zero) v = 0.f;
                    Cw[(size_t)gm * ldc + gn] = v;
                }
            }
        }
}

// -------------------- fp16 single-product GEMM (128x128, 2-stage) --------------------
// C[M,N] = A[M,512] @ B[N,512]^T + bias, row-masked. 1/3 the MMAs of bf16x3.
#define FMATB (128 * SST)

__global__ void __launch_bounds__(256, 2) gemm_f16(
    const fp16* __restrict__ A, const fp16* __restrict__ B,
    float* __restrict__ C, int M, int N, int K,
    const float* __restrict__ bias, const int* __restrict__ mlen)
{
    extern __shared__ __align__(16) char smraw[];
    fp16* sm = (fp16*)smraw;                     // [2][2][FMATB]

    const int tid = threadIdx.x;
    const int bm = blockIdx.y * 128, bn = blockIdx.x * 128;
    const int w = tid >> 5, lane = tid & 31;
    const int wm = w >> 2, wn = w & 3;
    const int g = lane >> 2, tg = lane & 3;
    const int lrow = lane & 15, lcol = (lane >> 4) * 8;
    const int ldrow = tid >> 1, ldch = (tid & 1) * 2;

    const fp16* aSrc = A + (size_t)(bm + ldrow) * K + ldch * 8;
    int gn_l = bn + ldrow;
    uint32_t szb = (gn_l < N) ? 16u : 0u;
    if (gn_l >= N) gn_l = 0;
    const fp16* bSrc = B + (size_t)gn_l * K + ldch * 8;
    const uint32_t da = su(sm + ldrow * SST + ldch * 8);
    const uint32_t db = da + FMATB * 2;

    float acc[4][4][4];
#pragma unroll
    for (int i = 0; i < 4; i++)
#pragma unroll
        for (int j = 0; j < 4; j++)
#pragma unroll
            for (int q = 0; q < 4; q++) acc[i][j][q] = 0.f;

    auto issue = [&](int stg, int k0) {
        uint32_t so = (uint32_t)(stg * 2 * FMATB) * 2;
        cpa16(da + so,      aSrc + k0,     16);
        cpa16(da + so + 16, aSrc + k0 + 8, 16);
        cpa16(db + so,      bSrc + k0,     szb);
        cpa16(db + so + 16, bSrc + k0 + 8, szb);
    };

    const int niter = K / 32;
    issue(0, 0);
    cpcommit();
    int st = 0;
    for (int it = 0; it < niter; ++it) {
        if (it + 1 < niter) {
            issue(st ^ 1, (it + 1) * 32);
            cpcommit();
            cpwait<1>();
        } else {
            cpwait<0>();
        }
        __syncthreads();
        const fp16* base = sm + st * 2 * FMATB;
#pragma unroll
        for (int ks = 0; ks < 32; ks += 16) {
            uint32_t ah[4][4], bh[2][4];
#pragma unroll
            for (int mi = 0; mi < 4; mi++)
                ldsm4(ah[mi], su(base + (wm * 64 + mi * 16 + lrow) * SST + ks + lcol));
#pragma unroll
            for (int p = 0; p < 2; p++)
                ldsm4(bh[p], su(base + FMATB + (wn * 32 + p * 16 + lrow) * SST + ks + lcol));
#pragma unroll
            for (int mi = 0; mi < 4; mi++)
#pragma unroll
                for (int ni = 0; ni < 4; ni++) {
                    const int p = ni >> 1, q = ni & 1;
                    mmah(acc[mi][ni], ah[mi], bh[p][q], bh[p][q + 2]);
                }
        }
        __syncthreads();
        st ^= 1;
    }

#pragma unroll
    for (int mi = 0; mi < 4; mi++)
#pragma unroll
        for (int ni = 0; ni < 4; ni++) {
            int gn0 = bn + wn * 32 + ni * 8 + tg * 2;
#pragma unroll
            for (int half = 0; half < 2; half++) {
                int gm = bm + wm * 64 + mi * 16 + g + half * 8;
                if (gm >= M) continue;
                bool zero = (mlen[gm / TT] <= (gm % TT));
#pragma unroll
                for (int q = 0; q < 2; q++) {
                    int gn = gn0 + q;
                    if (gn >= N) continue;
                    float v = acc[mi][ni][half * 2 + q] + bias[gn];
                    if (zero) v = 0.f;
                    C[(size_t)gm * N + gn] = v;
                }
            }
        }
}

// -------------------- cheap grid barrier (acq/rel) --------------------
__device__ __forceinline__ void gridbar() {
    __syncthreads();
    if (threadIdx.x == 0) {
        unsigned gen = *(volatile unsigned*)&g_bargen;
        unsigned old;
        asm volatile("atom.add.release.gpu.u32 %0,[%1],1;"
                     : "=r"(old) : "l"(&g_barcnt) : "memory");
        if (old == gridDim.x - 1) {
            g_barcnt = 0;
            asm volatile("st.release.gpu.u32 [%0],%1;"
                         :: "l"(&g_bargen), "r"(gen + 1) : "memory");
        } else {
            unsigned v;
            do {
                asm volatile("ld.acquire.gpu.u32 %0,[%1];"
                             : "=r"(v) : "l"(&g_bargen) : "memory");
            } while (v == gen);
        }
    }
    __syncthreads();
}

// -------------------- persistent recurrence kernel --------------------
#define RST 72
#define RMATB (128 * RST)

__global__ __launch_bounds__(256, 1) void recur_kernel(
    const float* __restrict__ b_hh,
    const int*   __restrict__ lengths,
    const float* __restrict__ spatial,
    const float* __restrict__ bg,
    const float* __restrict__ wh,
    const float* __restrict__ bh_att,
    const float* __restrict__ b_init_h,
    const float* __restrict__ b_init_m,
    const float* __restrict__ b_ih,
    const float* __restrict__ bv)
{
    extern __shared__ __align__(16) char dsm[];
    bf16* sAh = (bf16*)dsm;
    bf16* sAl = sAh + RMATB;
    bf16* sBh = sAl + RMATB;
    bf16* sBl = sBh + RMATB;
    float* sh_gh    = (float*)(dsm + 4 * RMATB * 2);
    float* sh_z     = sh_gh + 52;
    float* sh_alpha = sh_z + 52;

    const int c = blockIdx.x;
    const int tid = threadIdx.x;
    const int kc = c & 7, cg = c >> 3, kbase = kc * 64;
    const int b = c;
    const int w = tid >> 5, lane = tid & 31;
    const int wm = w >> 2, wn = w & 3;
    const int g = lane >> 2, tg = lane & 3;
    const int lrow = lane & 15, lcol = (lane >> 4) * 8;
    const int wid = w;
    const float bh0 = bh_att[0];

    float hp[2], mr[2], gb[8];
    int len = 0;

    if (b < BQ) {
        len = lengths[b];
#pragma unroll
        for (int j = 0; j < 12; j++) {
            int n = tid + j * 256;
            float v = g_ipart[0][b * 3072 + n] + g_ipart[1][b * 3072 + n]
                    + g_ipart[2][b * 3072 + n] + g_ipart[3][b * 3072 + n];
            if (j < 2) {
                v += b_init_h[n];
                hp[j] = v;
                bf16 hh = __float2bfloat16(v);
                g_hhi[b * DD + n] = hh;
                g_hlo[b * DD + n] = __float2bfloat16(v - __bfloat162float(hh));
            } else if (j < 4) {
                mr[j - 2] = v + b_init_m[n - 512];
            } else {
                int col = n - 1024;
                gb[j - 4] = v + b_ih[col] + b_hh[col];
            }
        }
        for (int i = tid; i < KK_ * KK_; i += 256) {
            int r = b * KK_ + i / KK_, q = i % KK_;
            g_vproj[(size_t)r * KK_ + q] =
                g_vpart[0][(size_t)r * KK_ + q] + g_vpart[1][(size_t)r * KK_ + q] + bv[q];
        }
    }
#pragma unroll
    for (int j = 0; j < 4; j++) {
        int cid = tid + j * 256;
        int row = cid >> 3, ch = cid & 7;
        *(float4*)(sBh + row * RST + ch * 8) =
            *(const float4*)(g_wc2hi + (size_t)(cg * 128 + row) * DD + kbase + ch * 8);
        *(float4*)(sBl + row * RST + ch * 8) =
            *(const float4*)(g_wc2lo + (size_t)(cg * 128 + row) * DD + kbase + ch * 8);
    }
    gridbar();

    for (int t = 0; t <= TT; t++) {
        {
#pragma unroll
            for (int j = 0; j < 4; j++) {
                int cid = tid + j * 256;
                int row = cid >> 3, ch = cid & 7;
                *(float4*)(sAh + row * RST + ch * 8) =
                    *(const float4*)(g_hhi + (size_t)row * DD + kbase + ch * 8);
                *(float4*)(sAl + row * RST + ch * 8) =
                    *(const float4*)(g_hlo + (size_t)row * DD + kbase + ch * 8);
            }
            __syncthreads();

            float acc[4][4][4];
#pragma unroll
            for (int i = 0; i < 4; i++)
#pragma unroll
                for (int j = 0; j < 4; j++)
#pragma unroll
                    for (int q = 0; q < 4; q++) acc[i][j][q] = 0.f;

#pragma unroll
            for (int ks = 0; ks < 64; ks += 16)
                mma_tile_k16<RST>(sAh, sAl, sBh, sBl, ks, wm, wn, lrow, lcol, acc);

#pragma unroll
            for (int mi = 0; mi < 4; mi++)
#pragma unroll
                for (int ni = 0; ni < 4; ni++) {
                    int gn0 = wn * 32 + ni * 8 + tg * 2;
#pragma unroll
                    for (int half = 0; half < 2; half++) {
                        int gm = wm * 64 + mi * 16 + g + half * 8;
                        float* pr = g_part + (size_t)gm * (8 * NW) + kc * NW + cg * 128 + gn0;
                        pr[0] = acc[mi][ni][half * 2 + 0];
                        pr[1] = acc[mi][ni][half * 2 + 1];
                    }
                }
        }
        gridbar();
        if (b < BQ) {
            const float* pp = g_part + (size_t)b * (8 * NW);
            if (t >= 1 && len > t - 1) {
                if (tid < KK_) {
                    float s = bg[tid];
#pragma unroll
                    for (int q = 0; q < 8; q++) s += pp[q * NW + 2048 + tid];
                    sh_gh[tid] = s;
                }
                __syncthreads();
                for (int k = wid; k < KK_; k += 8) {
                    const float* vp = g_vproj + (size_t)(b * KK_ + k) * KK_;
                    float s = 0.f;
                    for (int q = lane; q < KK_; q += 32) s += ftanh(vp[q] + sh_gh[q]) * wh[q];
#pragma unroll
                    for (int o = 16; o; o >>= 1) s += __shfl_xor_sync(0xffffffffu, s, o);
                    if (lane == 0) sh_z[k] = s + bh0;
                }
                __syncthreads();
                if (wid == 0) {
                    float mx = -3.0e38f;
                    for (int k = lane; k < KK_; k += 32) mx = fmaxf(mx, sh_z[k]);
#pragma unroll
                    for (int o = 16; o; o >>= 1) mx = fmaxf(mx, __shfl_xor_sync(0xffffffffu, mx, o));
                    float sm = 0.f;
                    for (int k = lane; k < KK_; k += 32) { float e = __expf(sh_z[k] - mx); sh_alpha[k] = e; sm += e; }
#pragma unroll
                    for (int o = 16; o; o >>= 1) sm += __shfl_xor_sync(0xffffffffu, sm, o);
                    float inv = 1.f / sm;
                    for (int k = lane; k < KK_; k += 32) sh_alpha[k] *= inv;
                }
                __syncthreads();
                const float* sp = spatial + (size_t)b * KK_ * DD;
#pragma unroll
                for (int j = 0; j < 2; j++) {
                    int d = tid + j * 256;
                    float cc = 0.f;
#pragma unroll
                    for (int k = 0; k < KK_; k++) cc = fmaf(sh_alpha[k], sp[(size_t)k * DD + d], cc);
                    float sv = cc + hp[j];
                    g_sf[(size_t)(b * TT + t - 1) * DD + d] = __float2half(sv);
                }
            }
            if (t < TT && len > t) {
                const float* gx = g_gatesx + (size_t)(b * TT + t) * G4;
#pragma unroll
                for (int j = 0; j < 2; j++) {
                    int d = tid + j * 256;
                    float gi = gx[d]        + gb[j];
                    float gf = gx[512 + d]  + gb[2 + j];
                    float gg = gx[1024 + d] + gb[4 + j];
                    float go = gx[1536 + d] + gb[6 + j];
#pragma unroll
                    for (int q = 0; q < 8; q++) {
                        const float* p = pp + q * NW;
                        gi += p[d]; gf += p[512 + d]; gg += p[1024 + d]; go += p[1536 + d];
                    }
                    float ig = fsig(gi), fg = fsig(gf), og = fsig(go);
                    float gt = ftanh(gg);
                    float mn = fg * mr[j] + ig * gt;
                    float hv = og * ftanh(mn);
                    mr[j] = mn;
                    hp[j] = hv;
                    bf16 hh = __float2bfloat16(hv);
                    g_hhi[(size_t)b * DD + d] = hh;
                    g_hlo[(size_t)b * DD + d] = __float2bfloat16(hv - __bfloat162float(hh));
                }
            }
        }
        gridbar();
    }
}

// -------------------- launch --------------------
extern "C" void kernel_launch(void* const* d_in, const int* in_sizes, int n_in,
                              void* d_out, int out_size)
{
    const float* spatial      = (const float*)d_in[0];
    const float* global_feats = (const float*)d_in[1];
    const int*   captions     = (const int*)d_in[2];
    const int*   lengths      = (const int*)d_in[3];
    const float* emb          = (const float*)d_in[4];
    const float* W_init_h     = (const float*)d_in[5];
    const float* b_init_h     = (const float*)d_in[6];
    const float* W_init_m     = (const float*)d_in[7];
    const float* b_init_m     = (const float*)d_in[8];
    const float* W_ih         = (const float*)d_in[9];
    const float* b_ih         = (const float*)d_in[10];
    const float* W_hh         = (const float*)d_in[11];
    const float* b_hh         = (const float*)d_in[12];
    const float* Wv           = (const float*)d_in[13];
    const float* bv           = (const float*)d_in[14];
    const float* Wg           = (const float*)d_in[15];
    const float* bg           = (const float*)d_in[16];
    const float* wh           = (const float*)d_in[17];
    const float* bh_att       = (const float*)d_in[18];
    const float* Wp           = (const float*)d_in[19];
    const float* bp           = (const float*)d_in[20];
    float* out = (float*)d_out;

#define GETP(var, sym) void* var; cudaGetSymbolAddress(&var, sym)
    GETP(p_embhi, g_embhi);  GETP(p_emblo, g_emblo);
    GETP(p_glhi, g_glhi);    GETP(p_gllo, g_gllo);
    GETP(p_wihehi, g_wihehi);GETP(p_wihelo, g_wihelo);
    GETP(p_wcathi, g_wcathi);GETP(p_wcatlo, g_wcatlo);
    GETP(p_wc2hi, g_wc2hi);  GETP(p_wc2lo, g_wc2lo);
    GETP(p_wvhi, g_wvhi);    GETP(p_wvlo, g_wvlo);
    GETP(p_sphi, g_sphi);    GETP(p_splo, g_splo);
    GETP(p_wpf, g_wpf);      GETP(p_sf, g_sf);
    GETP(p_gatesx, g_gatesx);
    GETP(p_ipart, g_ipart);  GETP(p_vpart, g_vpart);
#undef GETP

    const int GSM  = 2 * 4 * SMATB * 2;                      // 81920 B
    const int FSM  = 2 * 2 * FMATB * 2;                      // 40960 B
    const int RSM  = 4 * RMATB * 2 + (3 * 52) * 4;
    cudaFuncSetAttribute(gemm_hl, cudaFuncAttributeMaxDynamicSharedMemorySize, GSM);
    cudaFuncSetAttribute(gemm_f16, cudaFuncAttributeMaxDynamicSharedMemorySize, FSM);
    cudaFuncSetAttribute(recur_kernel, cudaFuncAttributeMaxDynamicSharedMemorySize, RSM);

    // ---- 1. split bf16x3 operands (Wp handled separately as fp16) ----
    SegArr sa;
    long long pos = 0;
    auto seg = [&](int i, const float* src, void* hi, void* lo, int srcld, int cols, int rows) {
        sa.s[i].src = (const float4*)src;
        sa.s[i].hi = (uint2*)hi;  sa.s[i].lo = (uint2*)lo;
        sa.s[i].srcld4 = srcld / 4;
        sa.s[i].lc4 = (cols / 4 == 64) ? 6 : 7;
        sa.s[i].start = pos;
        pos += (long long)rows * (cols / 4);
    };
    seg(0, global_feats, p_glhi, p_gllo, DD, DD, BQ);
    seg(1, W_init_h, p_wcathi, p_wcatlo, DD, DD, DD);
    seg(2, W_init_m, (bf16*)p_wcathi + 512 * DD, (bf16*)p_wcatlo + 512 * DD, DD, DD, DD);
    seg(3, W_ih, p_wihehi, p_wihelo, EE + DD, EE, G4);
    seg(4, W_ih + EE, (bf16*)p_wcathi + 1024 * DD, (bf16*)p_wcatlo + 1024 * DD, EE + DD, DD, G4);
    seg(5, W_hh, p_wc2hi, p_wc2lo, DD, DD, G4);
    seg(6, Wg, (bf16*)p_wc2hi + 2048 * DD, (bf16*)p_wc2lo + 2048 * DD, DD, DD, KK_);
    seg(7, Wv, p_wvhi, p_wvlo, DD, DD, KK_);
    seg(8, spatial, p_sphi, p_splo, DD, DD, BQ * KK_);
    sa.total = pos;
    split_all<<<(unsigned)((pos + 255) / 256), 256>>>(sa);

    // ---- 2. Wp -> fp16 ----
    conv_half<<<(VV * DD / 4 + 255) / 256, 256>>>(
        (const float4*)Wp, (uint2*)p_wpf, VV * DD / 4);

    // ---- 3. gather caption embeddings (bf16 hi/lo) ----
    gather_emb<<<(BQ * TT * (EE / 4) + 255) / 256, 256>>>(captions, emb);

    // ---- 4. vproj partials: spatial @ Wv^T, split-K x2 ----
    gemm_hl<<<dim3(1, 49, 2), 256, GSM>>>((bf16*)p_sphi, (bf16*)p_splo, DD,
        (bf16*)p_wvhi, (bf16*)p_wvlo, DD, nullptr, KK_, BQ * KK_, KK_, 256,
        nullptr, nullptr, 1, (float*)p_vpart, (long)BQ * KK_ * KK_);

    // ---- 5. gates_x = embseq @ W_ih[:,:E]^T ----
    gemm_hl<<<dim3(16, 20), 256, GSM>>>((bf16*)p_embhi, (bf16*)p_emblo, EE,
        (bf16*)p_wihehi, (bf16*)p_wihelo, EE, (float*)p_gatesx, G4, BQ * TT, G4, EE,
        nullptr, nullptr, 1, nullptr, 0);

    // ---- 6. init partials: global @ [Winit_h;Winit_m;W_ihD]^T, split-K x4 ----
    gemm_hl<<<dim3(24, 1, 4), 256, GSM>>>((bf16*)p_glhi, (bf16*)p_gllo, DD,
        (bf16*)p_wcathi, (bf16*)p_wcatlo, DD, nullptr, 3072, BQ, 3072, 128,
        nullptr, nullptr, 1, (float*)p_ipart, (long)BQ * 3072);

    // ---- 7. recurrence (emits s in fp16) ----
    recur_kernel<<<136, 256, RSM>>>(b_hh, lengths, spatial, bg, wh, bh_att,
                                    b_init_h, b_init_m, b_ih, bv);

    // ---- 8. logits = s @ Wp^T + bp (masked), fp16 single-product ----
    gemm_f16<<<dim3(79, 20), 256, FSM>>>((fp16*)p_sf, (fp16*)p_wpf,
        out, BQ * TT, VV, DD, bp, lengths);
}

// round 10
// speedup vs baseline: 1.4098x; 1.0295x over previous
#include <cuda_runtime.h>
#include <cuda_fp16.h>
#include <math.h>
#include <stdint.h>

#define BQ  128
#define KK_ 49
#define DD  512
#define EE  256
#define VV  10000
#define TT  20
#define G4  2048
#define NW  2176          // padded gates+Wg width: 2048 + 49 -> 17*128
typedef __half fp16;

// -------------------- device scratch (static) --------------------
__device__ __align__(128) fp16 g_embf[BQ*TT*EE];
__device__ __align__(128) fp16 g_glf[BQ*DD];
__device__ __align__(128) fp16 g_wihef[G4*EE];
__device__ __align__(128) fp16 g_wcatf[3072*DD];   // [Winit_h;Winit_m;W_ih_D]
__device__ __align__(128) fp16 g_wc2f[NW*DD];      // [W_hh;Wg;0pad]
__device__ __align__(128) fp16 g_wvf[KK_*DD];
__device__ __align__(128) fp16 g_wpf[VV*DD];
__device__ __align__(128) fp16 g_spf[BQ*KK_*DD];
__device__ __align__(128) fp16 g_hf[BQ*DD];
__device__ __align__(128) fp16 g_sf[BQ*TT*DD];
__device__ __align__(128) float g_gatesx[BQ*TT*G4];
__device__ __align__(128) float g_vproj[BQ*KK_*KK_];
__device__ __align__(128) float g_part[BQ*8*NW];
__device__ __align__(128) float g_ipart[4][BQ*3072];
__device__ __align__(128) float g_vpart[2][BQ*KK_*KK_];
__device__ unsigned g_bgrp[17];    // 2-level barrier: group counters (monotonic)
__device__ unsigned g_brt;         // root counter (monotonic)
__device__ unsigned g_bgen;        // generation (monotonic)

// -------------------- helpers --------------------
__device__ __forceinline__ uint32_t su(const void* p) {
    return (uint32_t)__cvta_generic_to_shared(p);
}
__device__ __forceinline__ void cpa16(uint32_t sa, const void* ga, uint32_t sz) {
    asm volatile("cp.async.cg.shared.global [%0],[%1],16,%2;\n" :: "r"(sa), "l"(ga), "r"(sz));
}
__device__ __forceinline__ void cpcommit() { asm volatile("cp.async.commit_group;\n"); }
template<int N> __device__ __forceinline__ void cpwait() {
    asm volatile("cp.async.wait_group %0;\n" :: "n"(N));
}
__device__ __forceinline__ void ldsm4(uint32_t* r, uint32_t a) {
    asm volatile("ldmatrix.sync.aligned.m8n8.x4.shared.b16 {%0,%1,%2,%3},[%4];\n"
                 : "=r"(r[0]), "=r"(r[1]), "=r"(r[2]), "=r"(r[3]) : "r"(a));
}
__device__ __forceinline__ void mmah(float* c, const uint32_t* a, uint32_t b0, uint32_t b1) {
    asm volatile(
        "mma.sync.aligned.m16n8k16.row.col.f32.f16.f16.f32 "
        "{%0,%1,%2,%3},{%4,%5,%6,%7},{%8,%9},{%0,%1,%2,%3};\n"
        : "+f"(c[0]), "+f"(c[1]), "+f"(c[2]), "+f"(c[3])
        : "r"(a[0]), "r"(a[1]), "r"(a[2]), "r"(a[3]), "r"(b0), "r"(b1));
}
__device__ __forceinline__ float fsig(float x) { return 1.f / (1.f + __expf(-x)); }
__device__ __forceinline__ float ftanh(float x) {
    float e = __expf(2.f * x);
    return 1.f - 2.f / (e + 1.f);
}

// -------------------- fp32 -> fp16 segmented converter --------------------
struct Seg { const float4* src; uint2* dst; int srcld4; int lc4; long long start; };
struct SegArr { Seg s[10]; long long total; };

__global__ void conv_all(SegArr sa) {
    long long i = (long long)blockIdx.x * blockDim.x + threadIdx.x;
    if (i >= sa.total) return;
    int k = 0;
#pragma unroll
    for (int j = 1; j < 10; j++) if (i >= sa.s[j].start) k = j;
    Seg sg = sa.s[k];
    long long idx = i - sg.start;
    int row = (int)(idx >> sg.lc4);
    int c   = (int)(idx & ((1 << sg.lc4) - 1));
    float4 v = sg.src[(long long)row * sg.srcld4 + c];
    __half2 a = __floats2half2_rn(v.x, v.y);
    __half2 b = __floats2half2_rn(v.z, v.w);
    uint2 o;
    o.x = *reinterpret_cast<uint32_t*>(&a);
    o.y = *reinterpret_cast<uint32_t*>(&b);
    sg.dst[idx] = o;
}

// -------------------- embedding gather (emits fp16) --------------------
__global__ void gather_emb(const int* __restrict__ cap, const float* __restrict__ emb) {
    int i = blockIdx.x * blockDim.x + threadIdx.x;
    if (i >= BQ * TT * (EE / 4)) return;
    int m = i >> 6, e4 = i & 63;
    int tok = cap[m];
    float4 v = reinterpret_cast<const float4*>(emb)[(size_t)tok * 64 + e4];
    __half2 a = __floats2half2_rn(v.x, v.y);
    __half2 b = __floats2half2_rn(v.z, v.w);
    uint2 o;
    o.x = *reinterpret_cast<uint32_t*>(&a);
    o.y = *reinterpret_cast<uint32_t*>(&b);
    reinterpret_cast<uint2*>(g_embf)[(size_t)m * 64 + e4] = o;
}

// -------------------- generalized fp16 GEMM (128x128, 2-stage pipeline) --------------
// C[M,N] = A[M,K]@B[N,K]^T (+bias, row zero-mask, optional split-K partials via z)
#define SST   40
#define FMATB (128 * SST)

__global__ void __launch_bounds__(256, 2) gemm_f16(
    const fp16* __restrict__ A, int lda,
    const fp16* __restrict__ B, int ldb,
    float* __restrict__ C, int ldc, int M, int N, int K,   // K = per-z slice
    const float* __restrict__ bias,
    const int* __restrict__ mlen, int maskT,
    float* __restrict__ Cpart, long partStride)
{
    extern __shared__ __align__(16) char smraw[];
    fp16* sm = (fp16*)smraw;                     // [2][2][FMATB]

    const int tid = threadIdx.x;
    const int bm = blockIdx.y * 128, bn = blockIdx.x * 128;
    const int kz = blockIdx.z;
    float* Cw = Cpart ? (Cpart + (size_t)kz * partStride) : C;

    const int w = tid >> 5, lane = tid & 31;
    const int wm = w >> 2, wn = w & 3;
    const int g = lane >> 2, tg = lane & 3;
    const int lrow = lane & 15, lcol = (lane >> 4) * 8;
    const int ldrow = tid >> 1, ldch = (tid & 1) * 2;

    const fp16* aSrc = A + (size_t)kz * K + (size_t)(bm + ldrow) * lda + ldch * 8;
    int gn_l = bn + ldrow;
    uint32_t szb = (gn_l < N) ? 16u : 0u;
    if (gn_l >= N) gn_l = 0;
    const fp16* bSrc = B + (size_t)kz * K + (size_t)gn_l * ldb + ldch * 8;
    const uint32_t da = su(sm + ldrow * SST + ldch * 8);
    const uint32_t db = da + FMATB * 2;

    float acc[4][4][4];
#pragma unroll
    for (int i = 0; i < 4; i++)
#pragma unroll
        for (int j = 0; j < 4; j++)
#pragma unroll
            for (int q = 0; q < 4; q++) acc[i][j][q] = 0.f;

    auto issue = [&](int stg, int k0) {
        uint32_t so = (uint32_t)(stg * 2 * FMATB) * 2;
        cpa16(da + so,      aSrc + k0,     16);
        cpa16(da + so + 16, aSrc + k0 + 8, 16);
        cpa16(db + so,      bSrc + k0,     szb);
        cpa16(db + so + 16, bSrc + k0 + 8, szb);
    };

    const int niter = K / 32;
    issue(0, 0);
    cpcommit();
    int st = 0;
    for (int it = 0; it < niter; ++it) {
        if (it + 1 < niter) {
            issue(st ^ 1, (it + 1) * 32);
            cpcommit();
            cpwait<1>();
        } else {
            cpwait<0>();
        }
        __syncthreads();
        const fp16* base = sm + st * 2 * FMATB;
#pragma unroll
        for (int ks = 0; ks < 32; ks += 16) {
            uint32_t ah[4][4], bh[2][4];
#pragma unroll
            for (int mi = 0; mi < 4; mi++)
                ldsm4(ah[mi], su(base + (wm * 64 + mi * 16 + lrow) * SST + ks + lcol));
#pragma unroll
            for (int p = 0; p < 2; p++)
                ldsm4(bh[p], su(base + FMATB + (wn * 32 + p * 16 + lrow) * SST + ks + lcol));
#pragma unroll
            for (int mi = 0; mi < 4; mi++)
#pragma unroll
                for (int ni = 0; ni < 4; ni++) {
                    const int p = ni >> 1, q = ni & 1;
                    mmah(acc[mi][ni], ah[mi], bh[p][q], bh[p][q + 2]);
                }
        }
        __syncthreads();
        st ^= 1;
    }

#pragma unroll
    for (int mi = 0; mi < 4; mi++)
#pragma unroll
        for (int ni = 0; ni < 4; ni++) {
            int gn0 = bn + wn * 32 + ni * 8 + tg * 2;
#pragma unroll
            for (int half = 0; half < 2; half++) {
                int gm = bm + wm * 64 + mi * 16 + g + half * 8;
                if (gm >= M) continue;
                bool zero = mlen ? (mlen[gm / maskT] <= (gm % maskT)) : false;
#pragma unroll
                for (int q = 0; q < 2; q++) {
                    int gn = gn0 + q;
                    if (gn >= N) continue;
                    float v = acc[mi][ni][half * 2 + q];
                    if (bias) v += bias[gn];
                    if (zero) v = 0.f;
                    Cw[(size_t)gm * ldc + gn] = v;
                }
            }
        }
}

// -------------------- 2-level grid barrier (monotonic, replay-safe) --------------------
// 136 CTAs = 17 groups x 8. rr = absolute round (base generation + local round).
__device__ __forceinline__ void gridbar2(int grp, unsigned rr) {
    __syncthreads();
    if (threadIdx.x == 0) {
        unsigned old;
        asm volatile("atom.add.release.gpu.u32 %0,[%1],1;"
                     : "=r"(old) : "l"(&g_bgrp[grp]) : "memory");
        if (old == rr * 8u + 7u) {
            unsigned old2;
            asm volatile("atom.add.release.gpu.u32 %0,[%1],1;"
                         : "=r"(old2) : "l"(&g_brt) : "memory");
            if (old2 == rr * 17u + 16u) {
                asm volatile("st.release.gpu.u32 [%0],%1;"
                             :: "l"(&g_bgen), "r"(rr + 1u) : "memory");
            }
        }
        unsigned v;
        do {
            asm volatile("ld.acquire.gpu.u32 %0,[%1];"
                         : "=r"(v) : "l"(&g_bgen) : "memory");
        } while ((int)(v - (rr + 1u)) < 0);
    }
    __syncthreads();
}

// -------------------- persistent recurrence kernel (fp16 MMA) --------------------
#define RST 72
#define RMATB (128 * RST)

__global__ __launch_bounds__(256, 1) void recur_kernel(
    const float* __restrict__ b_hh,
    const int*   __restrict__ lengths,
    const float* __restrict__ bg,
    const float* __restrict__ wh,
    const float* __restrict__ bh_att,
    const float* __restrict__ b_init_h,
    const float* __restrict__ b_init_m,
    const float* __restrict__ b_ih,
    const float* __restrict__ bv)
{
    extern __shared__ __align__(16) char dsm[];
    fp16* sA = (fp16*)dsm;             // [128][RST]
    fp16* sB = sA + RMATB;             // [128][RST]
    float* sh_gh    = (float*)(dsm + 2 * RMATB * 2);
    float* sh_z     = sh_gh + 52;
    float* sh_alpha = sh_z + 52;

    const int c = blockIdx.x;
    const int tid = threadIdx.x;
    const int kc = c & 7, cg = c >> 3, kbase = kc * 64;   // cg in 0..16
    const int grp = cg;                                   // barrier group
    const int b = c;                                      // phase2 owner (b<128)
    const int w = tid >> 5, lane = tid & 31;
    const int wm = w >> 2, wn = w & 3;
    const int g = lane >> 2, tg = lane & 3;
    const int lrow = lane & 15, lcol = (lane >> 4) * 8;
    const int wid = w;
    const float bh0 = bh_att[0];

    // per-launch barrier base (stable at kernel entry; replay-safe)
    unsigned rbase;
    asm volatile("ld.acquire.gpu.u32 %0,[%1];" : "=r"(rbase) : "l"(&g_bgen) : "memory");
    unsigned round = 0;

    float hp[2], mr[2], gb[8];   // register-resident recurrent state
    int len = 0;

    // ---- prologue: per-batch init reduce + W slice preload ----
    if (b < BQ) {
        len = lengths[b];
#pragma unroll
        for (int j = 0; j < 12; j++) {
            int n = tid + j * 256;
            float v = g_ipart[0][b * 3072 + n] + g_ipart[1][b * 3072 + n]
                    + g_ipart[2][b * 3072 + n] + g_ipart[3][b * 3072 + n];
            if (j < 2) {
                v += b_init_h[n];
                hp[j] = v;
                g_hf[b * DD + n] = __float2half(v);
            } else if (j < 4) {
                mr[j - 2] = v + b_init_m[n - 512];
            } else {
                int col = n - 1024;
                gb[j - 4] = v + b_ih[col] + b_hh[col];
            }
        }
        for (int i = tid; i < KK_ * KK_; i += 256) {
            int r = b * KK_ + i / KK_, q = i % KK_;
            g_vproj[(size_t)r * KK_ + q] =
                g_vpart[0][(size_t)r * KK_ + q] + g_vpart[1][(size_t)r * KK_ + q] + bv[q];
        }
    }
#pragma unroll
    for (int j = 0; j < 4; j++) {
        int cid = tid + j * 256;
        int row = cid >> 3, ch = cid & 7;
        *(float4*)(sB + row * RST + ch * 8) =
            *(const float4*)(g_wc2f + (size_t)(cg * 128 + row) * DD + kbase + ch * 8);
    }
    gridbar2(grp, rbase + round); round++;   // h0 + vproj visible

    for (int t = 0; t <= TT; t++) {
        // ---------------- GEMM: [gates(t); gh(t-1)] = h(t-1) @ W_cat^T ----------------
        {
#pragma unroll
            for (int j = 0; j < 4; j++) {
                int cid = tid + j * 256;
                int row = cid >> 3, ch = cid & 7;
                *(float4*)(sA + row * RST + ch * 8) =
                    *(const float4*)(g_hf + (size_t)row * DD + kbase + ch * 8);
            }
            __syncthreads();

            float acc[4][4][4];
#pragma unroll
            for (int i = 0; i < 4; i++)
#pragma unroll
                for (int j = 0; j < 4; j++)
#pragma unroll
                    for (int q = 0; q < 4; q++) acc[i][j][q] = 0.f;

#pragma unroll
            for (int ks = 0; ks < 64; ks += 16) {
                uint32_t ah[4][4], bh2[2][4];
#pragma unroll
                for (int mi = 0; mi < 4; mi++)
                    ldsm4(ah[mi], su(sA + (wm * 64 + mi * 16 + lrow) * RST + ks + lcol));
#pragma unroll
                for (int p = 0; p < 2; p++)
                    ldsm4(bh2[p], su(sB + (wn * 32 + p * 16 + lrow) * RST + ks + lcol));
#pragma unroll
                for (int mi = 0; mi < 4; mi++)
#pragma unroll
                    for (int ni = 0; ni < 4; ni++) {
                        const int p = ni >> 1, q = ni & 1;
                        mmah(acc[mi][ni], ah[mi], bh2[p][q], bh2[p][q + 2]);
                    }
            }

#pragma unroll
            for (int mi = 0; mi < 4; mi++)
#pragma unroll
                for (int ni = 0; ni < 4; ni++) {
                    int gn0 = wn * 32 + ni * 8 + tg * 2;
#pragma unroll
                    for (int half = 0; half < 2; half++) {
                        int gm = wm * 64 + mi * 16 + g + half * 8;   // batch row
                        float* pr = g_part + (size_t)gm * (8 * NW) + kc * NW + cg * 128 + gn0;
                        pr[0] = acc[mi][ni][half * 2 + 0];
                        pr[1] = acc[mi][ni][half * 2 + 1];
                    }
                }
        }
        gridbar2(grp, rbase + round); round++;
        // ---------------- phase 2 (CTA b < 128) ----------------
        if (b < BQ) {
            const float* pp = g_part + (size_t)b * (8 * NW);
            // ---- attention for step t-1 ----
            if (t >= 1 && len > t - 1) {
                if (tid < KK_) {
                    float s = bg[tid];
#pragma unroll
                    for (int q = 0; q < 8; q++) s += pp[q * NW + 2048 + tid];
                    sh_gh[tid] = s;
                }
                __syncthreads();
                for (int k = wid; k < KK_; k += 8) {
                    const float* vp = g_vproj + (size_t)(b * KK_ + k) * KK_;
                    float s = 0.f;
                    for (int q = lane; q < KK_; q += 32) s += ftanh(vp[q] + sh_gh[q]) * wh[q];
#pragma unroll
                    for (int o = 16; o; o >>= 1) s += __shfl_xor_sync(0xffffffffu, s, o);
                    if (lane == 0) sh_z[k] = s + bh0;
                }
                __syncthreads();
                if (wid == 0) {
                    float mx = -3.0e38f;
                    for (int k = lane; k < KK_; k += 32) mx = fmaxf(mx, sh_z[k]);
#pragma unroll
                    for (int o = 16; o; o >>= 1) mx = fmaxf(mx, __shfl_xor_sync(0xffffffffu, mx, o));
                    float sm = 0.f;
                    for (int k = lane; k < KK_; k += 32) { float e = __expf(sh_z[k] - mx); sh_alpha[k] = e; sm += e; }
#pragma unroll
                    for (int o = 16; o; o >>= 1) sm += __shfl_xor_sync(0xffffffffu, sm, o);
                    float inv = 1.f / sm;
                    for (int k = lane; k < KK_; k += 32) sh_alpha[k] *= inv;
                }
                __syncthreads();
                const fp16* sp = g_spf + (size_t)b * KK_ * DD;
#pragma unroll
                for (int j = 0; j < 2; j++) {
                    int d = tid + j * 256;
                    float cc = 0.f;
#pragma unroll
                    for (int k = 0; k < KK_; k++)
                        cc = fmaf(sh_alpha[k], __half2float(sp[(size_t)k * DD + d]), cc);
                    float sv = cc + hp[j];
                    g_sf[(size_t)(b * TT + t - 1) * DD + d] = __float2half(sv);
                }
            }
            // ---- LSTM for step t ----
            if (t < TT && len > t) {
                const float* gx = g_gatesx + (size_t)(b * TT + t) * G4;
#pragma unroll
                for (int j = 0; j < 2; j++) {
                    int d = tid + j * 256;
                    float gi = gx[d]        + gb[j];
                    float gf = gx[512 + d]  + gb[2 + j];
                    float gg = gx[1024 + d] + gb[4 + j];
                    float go = gx[1536 + d] + gb[6 + j];
#pragma unroll
                    for (int q = 0; q < 8; q++) {
                        const float* p = pp + q * NW;
                        gi += p[d]; gf += p[512 + d]; gg += p[1024 + d]; go += p[1536 + d];
                    }
                    float ig = fsig(gi), fg = fsig(gf), og = fsig(go);
                    float gt = ftanh(gg);
                    float mn = fg * mr[j] + ig * gt;
                    float hv = og * ftanh(mn);
                    mr[j] = mn;
                    hp[j] = hv;
                    g_hf[(size_t)b * DD + d] = __float2half(hv);
                }
            }
        }
        gridbar2(grp, rbase + round); round++;
    }
}

// -------------------- launch --------------------
extern "C" void kernel_launch(void* const* d_in, const int* in_sizes, int n_in,
                              void* d_out, int out_size)
{
    const float* spatial      = (const float*)d_in[0];
    const float* global_feats = (const float*)d_in[1];
    const int*   captions     = (const int*)d_in[2];
    const int*   lengths      = (const int*)d_in[3];
    const float* emb          = (const float*)d_in[4];
    const float* W_init_h     = (const float*)d_in[5];
    const float* b_init_h     = (const float*)d_in[6];
    const float* W_init_m     = (const float*)d_in[7];
    const float* b_init_m     = (const float*)d_in[8];
    const float* W_ih         = (const float*)d_in[9];
    const float* b_ih         = (const float*)d_in[10];
    const float* W_hh         = (const float*)d_in[11];
    const float* b_hh         = (const float*)d_in[12];
    const float* Wv           = (const float*)d_in[13];
    const float* bv           = (const float*)d_in[14];
    const float* Wg           = (const float*)d_in[15];
    const float* bg           = (const float*)d_in[16];
    const float* wh           = (const float*)d_in[17];
    const float* bh_att       = (const float*)d_in[18];
    const float* Wp           = (const float*)d_in[19];
    const float* bp           = (const float*)d_in[20];
    float* out = (float*)d_out;

#define GETP(var, sym) void* var; cudaGetSymbolAddress(&var, sym)
    GETP(p_embf, g_embf);    GETP(p_glf, g_glf);
    GETP(p_wihef, g_wihef);  GETP(p_wcatf, g_wcatf);
    GETP(p_wc2f, g_wc2f);    GETP(p_wvf, g_wvf);
    GETP(p_wpf, g_wpf);      GETP(p_spf, g_spf);
    GETP(p_sf, g_sf);
    GETP(p_gatesx, g_gatesx);
    GETP(p_ipart, g_ipart);  GETP(p_vpart, g_vpart);
#undef GETP

    const int FSM = 2 * 2 * FMATB * 2;                       // 40960 B
    const int RSM = 2 * RMATB * 2 + (3 * 52) * 4;            // ~37.5 KB
    cudaFuncSetAttribute(gemm_f16, cudaFuncAttributeMaxDynamicSharedMemorySize, FSM);
    cudaFuncSetAttribute(recur_kernel, cudaFuncAttributeMaxDynamicSharedMemorySize, RSM);

    // ---- 1. convert all fp32 operands to fp16 ----
    SegArr sa;
    long long pos = 0;
    auto seg = [&](int i, const float* src, void* dst, int srcld, int cols, int rows) {
        sa.s[i].src = (const float4*)src;
        sa.s[i].dst = (uint2*)dst;
        sa.s[i].srcld4 = srcld / 4;
        sa.s[i].lc4 = (cols / 4 == 64) ? 6 : 7;
        sa.s[i].start = pos;
        pos += (long long)rows * (cols / 4);
    };
    seg(0, global_feats, p_glf, DD, DD, BQ);
    seg(1, W_init_h, p_wcatf, DD, DD, DD);
    seg(2, W_init_m, (fp16*)p_wcatf + 512 * DD, DD, DD, DD);
    seg(3, W_ih, p_wihef, EE + DD, EE, G4);
    seg(4, W_ih + EE, (fp16*)p_wcatf + 1024 * DD, EE + DD, DD, G4);
    seg(5, W_hh, p_wc2f, DD, DD, G4);
    seg(6, Wg, (fp16*)p_wc2f + 2048 * DD, DD, DD, KK_);
    seg(7, Wv, p_wvf, DD, DD, KK_);
    seg(8, Wp, p_wpf, DD, DD, VV);
    seg(9, spatial, p_spf, DD, DD, BQ * KK_);
    sa.total = pos;
    conv_all<<<(unsigned)((pos + 255) / 256), 256>>>(sa);

    // ---- 2. gather caption embeddings (fp16) ----
    gather_emb<<<(BQ * TT * (EE / 4) + 255) / 256, 256>>>(captions, emb);

    // ---- 3. vproj partials: spatial @ Wv^T, split-K x2 ----
    gemm_f16<<<dim3(1, 49, 2), 256, FSM>>>((fp16*)p_spf, DD, (fp16*)p_wvf, DD,
        nullptr, KK_, BQ * KK_, KK_, 256,
        nullptr, nullptr, 1, (float*)p_vpart, (long)BQ * KK_ * KK_);

    // ---- 4. gates_x = embseq @ W_ih[:,:E]^T ----
    gemm_f16<<<dim3(16, 20), 256, FSM>>>((fp16*)p_embf, EE, (fp16*)p_wihef, EE,
        (float*)p_gatesx, G4, BQ * TT, G4, EE,
        nullptr, nullptr, 1, nullptr, 0);

    // ---- 5. init partials: global @ [Winit_h;Winit_m;W_ihD]^T, split-K x4 ----
    gemm_f16<<<dim3(24, 1, 4), 256, FSM>>>((fp16*)p_glf, DD, (fp16*)p_wcatf, DD,
        nullptr, 3072, BQ, 3072, 128,
        nullptr, nullptr, 1, (float*)p_ipart, (long)BQ * 3072);

    // ---- 6. recurrence (fp16 MMA, 2-level barrier) ----
    recur_kernel<<<136, 256, RSM>>>(b_hh, lengths, bg, wh, bh_att,
                                    b_init_h, b_init_m, b_ih, bv);

    // ---- 7. logits = s @ Wp^T + bp (masked) ----
    gemm_f16<<<dim3(79, 20), 256, FSM>>>((fp16*)p_sf, DD, (fp16*)p_wpf, DD,
        out, VV, BQ * TT, VV, DD,
        bp, lengths, TT, nullptr, 0);
}